// round 15
// baseline (speedup 1.0000x reference)
#include <cuda_runtime.h>

#define W0 0.23037781330885523f
#define W1 0.7148465705525415f
#define W2 0.6308807679295904f
#define W3 (-0.02798376941698385f)
#define W4 (-0.18703481171888114f)
#define W5 0.030841381835986965f
#define W6 0.032883011666982945f
#define W7 (-0.010597401784997278f)

namespace {

constexpr int NROW = 2048;     // 32 * 64
constexpr int N    = 8192;
constexpr int L1   = 4099;     // dwt output lengths per level
constexpr int L2   = 2053;
constexpr int L3   = 1030;
constexpr int NT   = 256;      // threads per CTA -> 6 CTAs/SM, perfectly balanced loops

// shared memory: two regions, time-multiplexed.
//   R0 (4100): a1 (S1-S2b) -> a3 [0,1030) + d3 [1032,2062) (S3-S4)
//   R1 (4112): d1 (S1-S2a) -> a2 [0,2053) + d2 [2056,4109) (S2b-S3)
constexpr int OFF_R0 = 0;
constexpr int OFF_R1 = 4100;
constexpr int OFF_A3 = OFF_R0;
constexpr int OFF_D3 = OFF_R0 + 1032;
constexpr int OFF_A2 = OFF_R1;
constexpr int OFF_D2 = OFF_R1 + 2056;
constexpr int SM_FLOATS = 8212;    // 32848 B; 6 x (32848+1024) = 203KB < 228KB -> 6 CTAs/SM

__device__ __forceinline__ int symq(int q, int m) {
    q = (q < 0) ? (-q - 1) : q;
    return (q >= m) ? (2 * m - 1 - q) : q;
}

// 256-bit dense streaming global store (sm_100+): 8 consecutive floats, 32B-aligned.
__device__ __forceinline__ void stg256cs(float* p, float4 a, float4 b) {
    asm volatile("st.global.cs.v8.f32 [%0], {%1,%2,%3,%4,%5,%6,%7,%8};"
        :: "l"(p), "f"(a.x), "f"(a.y), "f"(a.z), "f"(a.w),
           "f"(b.x), "f"(b.y), "f"(b.z), "f"(b.w) : "memory");
}

// Scalar (boundary) analysis for one output index o.
__device__ __forceinline__ void dwt_scalar(const float* __restrict__ in, int m, int o,
                                           float& sA, float& sD) {
    const float RLO[8] = { W0,  W1,  W2,  W3,  W4,  W5,  W6,  W7};
    const float RHI[8] = { W7, -W6,  W5, -W4,  W3, -W2,  W1, -W0};
    const int base = 2 * o - 6;
    sA = 0.f; sD = 0.f;
    #pragma unroll
    for (int j = 0; j < 8; ++j) {
        float v = in[symq(base + j, m)];
        sA = fmaf(v, RLO[j], sA);
        sD = fmaf(v, RHI[j], sD);
    }
}

// One analysis level: lenOut = (m+5)/2 + 1. Pair-per-thread via 3x float4 loads
// (dense: 16B lane stride = load width). GLOB: input global read-once -> __ldcs.
template<bool GLOB>
__device__ __forceinline__ void dwt_level(const float* __restrict__ in, int m, int lenOut,
                                          float* __restrict__ oa, float* __restrict__ od) {
    const float4* __restrict__ in4 = reinterpret_cast<const float4*>(in);
    float2* __restrict__ oa2 = reinterpret_cast<float2*>(oa);
    float2* __restrict__ od2 = reinterpret_cast<float2*>(od);
    const int np = lenOut >> 1;
    for (int t = threadIdx.x; t < np; t += NT) {
        const int base = 4 * t - 6;
        float a0, d0, a1, d1;
        if (base >= 0 && base + 9 < m) {
            float4 q0, q1, q2;
            if (GLOB) {
                q0 = __ldcs(in4 + (t - 2));
                q1 = __ldcs(in4 + (t - 1));
                q2 = __ldcs(in4 + t);
            } else {
                q0 = in4[t - 2];
                q1 = in4[t - 1];
                q2 = in4[t];
            }
            a0 = fmaf(q0.z, W0, fmaf(q0.w, W1, fmaf(q1.x, W2, fmaf(q1.y, W3,
                 fmaf(q1.z, W4, fmaf(q1.w, W5, fmaf(q2.x, W6, q2.y * W7)))))));
            d0 = fmaf(q0.z, W7, fmaf(q0.w, -W6, fmaf(q1.x, W5, fmaf(q1.y, -W4,
                 fmaf(q1.z, W3, fmaf(q1.w, -W2, fmaf(q2.x, W1, q2.y * -W0)))))));
            a1 = fmaf(q1.x, W0, fmaf(q1.y, W1, fmaf(q1.z, W2, fmaf(q1.w, W3,
                 fmaf(q2.x, W4, fmaf(q2.y, W5, fmaf(q2.z, W6, q2.w * W7)))))));
            d1 = fmaf(q1.x, W7, fmaf(q1.y, -W6, fmaf(q1.z, W5, fmaf(q1.w, -W4,
                 fmaf(q2.x, W3, fmaf(q2.y, -W2, fmaf(q2.z, W1, q2.w * -W0)))))));
        } else {
            dwt_scalar(in, m, 2 * t,     a0, d0);
            dwt_scalar(in, m, 2 * t + 1, a1, d1);
        }
        oa2[t] = make_float2(a0, a1);
        od2[t] = make_float2(d0, d1);
    }
    if ((lenOut & 1) && threadIdx.x == 0) {   // odd tail output
        float a, d;
        dwt_scalar(in, m, lenOut - 1, a, d);
        oa[lenOut - 1] = a;
        od[lenOut - 1] = d;
    }
}

// One synthesis quad (4 outputs) from v0..v4 = in[2q..2q+4].
template<int HI>
__device__ __forceinline__ float4 idwt_quad(float v0, float v1, float v2, float v3, float v4) {
    const float E0 = HI ?  W1 : W6, E1 = HI ?  W3 : W4;
    const float E2 = HI ?  W5 : W2, E3 = HI ?  W7 : W0;
    const float O0 = HI ? -W0 : W7, O1 = HI ? -W2 : W5;
    const float O2 = HI ? -W4 : W3, O3 = HI ? -W6 : W1;
    float4 r;
    r.x = fmaf(v0, E0, fmaf(v1, E1, fmaf(v2, E2, v3 * E3)));
    r.y = fmaf(v0, O0, fmaf(v1, O1, fmaf(v2, O2, v3 * O3)));
    r.z = fmaf(v1, E0, fmaf(v2, E1, fmaf(v3, E2, v4 * E3)));
    r.w = fmaf(v1, O0, fmaf(v2, O1, fmaf(v3, O2, v4 * O3)));
    return r;
}

// Band3 single synthesis level, octet/thread: input m=4099 (4096 pairs = 1024 octets
// exactly). Octet s needs in[4s..4s+6], loaded as 2x DENSE float4 (16B stride = width).
// Max s=1023: reads in4[1024] = in[4096..4099] <= region 4112 (slack ok).
template<int HI>
__device__ __forceinline__ void idwt_vec8f4(const float* __restrict__ in,
                                            float* __restrict__ out) {
    const float4* __restrict__ in4 = reinterpret_cast<const float4*>(in);
    for (int s = threadIdx.x; s < 1024; s += NT) {
        float4 q0 = in4[s];        // in[4s..4s+3]
        float4 q1 = in4[s + 1];    // in[4s+4..4s+7]
        float4 a = idwt_quad<HI>(q0.x, q0.y, q0.z, q0.w, q1.x);
        float4 b = idwt_quad<HI>(q0.z, q0.w, q1.x, q1.y, q1.z);
        stg256cs(out + 8 * s, a, b);
    }
}

// Fused TWO synthesis levels (stage A = HIA, stage B = LO), octet/thread.
// Octet s = groups 2s,2s+1, window in[2s..2s+6] = in2[s..s+3] (DENSE float2,
// 8B stride = width). Max s=1023: in2[1026] -> in[2052..2053], slack ok.
template<int HIA>
__device__ __forceinline__ void idwt2_fused8(const float* __restrict__ in,
                                             float* __restrict__ out) {
    const float EA0 = HIA ?  W1 : W6, EA1 = HIA ?  W3 : W4;
    const float EA2 = HIA ?  W5 : W2, EA3 = HIA ?  W7 : W0;
    const float OA0 = HIA ? -W0 : W7, OA1 = HIA ? -W2 : W5;
    const float OA2 = HIA ? -W4 : W3, OA3 = HIA ? -W6 : W1;
    const float EB0 = W6, EB1 = W4, EB2 = W2, EB3 = W0;
    const float OB0 = W7, OB1 = W5, OB2 = W3, OB3 = W1;
    const float C00 = EB0*EA0 + EB1*OA0;
    const float C01 = EB0*EA1 + EB1*OA1 + EB2*EA0 + EB3*OA0;
    const float C02 = EB0*EA2 + EB1*OA2 + EB2*EA1 + EB3*OA1;
    const float C03 = EB0*EA3 + EB1*OA3 + EB2*EA2 + EB3*OA2;
    const float C04 =                     EB2*EA3 + EB3*OA3;
    const float C10 = OB0*EA0 + OB1*OA0;
    const float C11 = OB0*EA1 + OB1*OA1 + OB2*EA0 + OB3*OA0;
    const float C12 = OB0*EA2 + OB1*OA2 + OB2*EA1 + OB3*OA1;
    const float C13 = OB0*EA3 + OB1*OA3 + OB2*EA2 + OB3*OA2;
    const float C14 =                     OB2*EA3 + OB3*OA3;
    const float C20 = EB0*OA0;
    const float C21 = EB0*OA1 + EB1*EA0 + EB2*OA0;
    const float C22 = EB0*OA2 + EB1*EA1 + EB2*OA1 + EB3*EA0;
    const float C23 = EB0*OA3 + EB1*EA2 + EB2*OA2 + EB3*EA1;
    const float C24 =           EB1*EA3 + EB2*OA3 + EB3*EA2;
    const float C25 =                                EB3*EA3;
    const float C30 = OB0*OA0;
    const float C31 = OB0*OA1 + OB1*EA0 + OB2*OA0;
    const float C32 = OB0*OA2 + OB1*EA1 + OB2*OA1 + OB3*EA0;
    const float C33 = OB0*OA3 + OB1*EA2 + OB2*OA2 + OB3*EA1;
    const float C34 =           OB1*EA3 + OB2*OA3 + OB3*EA2;
    const float C35 =                                OB3*EA3;

    const float2* __restrict__ in2 = reinterpret_cast<const float2*>(in);
    for (int s = threadIdx.x; s < 1024; s += NT) {
        float2 w0 = in2[s];           // in[2s],   in[2s+1]
        float2 w1 = in2[s + 1];       // in[2s+2], in[2s+3]
        float2 w2 = in2[s + 2];       // in[2s+4], in[2s+5]
        float2 w3 = in2[s + 3];       // in[2s+6], in[2s+7] (slack)
        float v0 = w0.x, v1 = w0.y, v2 = w1.x, v3 = w1.y;
        float v4 = w2.x, v5 = w2.y, v6 = w3.x;
        float4 oA, oB;
        oA.x = fmaf(v0, C00, fmaf(v1, C01, fmaf(v2, C02, fmaf(v3, C03, v4 * C04))));
        oA.y = fmaf(v0, C10, fmaf(v1, C11, fmaf(v2, C12, fmaf(v3, C13, v4 * C14))));
        oA.z = fmaf(v0, C20, fmaf(v1, C21, fmaf(v2, C22,
               fmaf(v3, C23, fmaf(v4, C24, v5 * C25)))));
        oA.w = fmaf(v0, C30, fmaf(v1, C31, fmaf(v2, C32,
               fmaf(v3, C33, fmaf(v4, C34, v5 * C35)))));
        oB.x = fmaf(v1, C00, fmaf(v2, C01, fmaf(v3, C02, fmaf(v4, C03, v5 * C04))));
        oB.y = fmaf(v1, C10, fmaf(v2, C11, fmaf(v3, C12, fmaf(v4, C13, v5 * C14))));
        oB.z = fmaf(v1, C20, fmaf(v2, C21, fmaf(v3, C22,
               fmaf(v4, C23, fmaf(v5, C24, v6 * C25)))));
        oB.w = fmaf(v1, C30, fmaf(v2, C31, fmaf(v3, C32,
               fmaf(v4, C33, fmaf(v5, C34, v6 * C35)))));
        stg256cs(out + 8 * s, oA, oB);
    }
}

// ---- 3-level fused synthesis tables (inner HIA, then LO, then LO) ----
struct D3Tab { float d0[4][6]; float d1[4][7]; };

__host__ __device__ constexpr float safeE(const float* a, int i) {
    return (i >= 0 && i < 4) ? a[i] : 0.0f;
}

template<int HIA>
__host__ __device__ constexpr D3Tab make_d3() {
    float Ei[4] = {0, 0, 0, 0}, Oi[4] = {0, 0, 0, 0};
    if (HIA) {
        Ei[0] = W1; Ei[1] = W3; Ei[2] = W5; Ei[3] = W7;
        Oi[0] = -W0; Oi[1] = -W2; Oi[2] = -W4; Oi[3] = -W6;
    } else {
        Ei[0] = W6; Ei[1] = W4; Ei[2] = W2; Ei[3] = W0;
        Oi[0] = W7; Oi[1] = W5; Oi[2] = W3; Oi[3] = W1;
    }
    const float EA[4] = {W6, W4, W2, W0}, OA[4] = {W7, W5, W3, W1};
    const float EB[4] = {W6, W4, W2, W0}, OB[4] = {W7, W5, W3, W1};
    float C[4][6] = {};
    for (int k = 0; k < 6; ++k) {
        float c0 = 0, c1 = 0, c2 = 0, c3 = 0;
        for (int kp = 0; kp < 2; ++kp) {
            c0 += EB[2*kp] * safeE(EA, k - kp) + EB[2*kp+1] * safeE(OA, k - kp);
            c1 += OB[2*kp] * safeE(EA, k - kp) + OB[2*kp+1] * safeE(OA, k - kp);
            c2 += EB[2*kp] * safeE(OA, k - kp) + EB[2*kp+1] * safeE(EA, k - kp - 1);
            c3 += OB[2*kp] * safeE(OA, k - kp) + OB[2*kp+1] * safeE(EA, k - kp - 1);
        }
        C[0][k] = c0; C[1][k] = c1; C[2][k] = c2; C[3][k] = c3;
    }
    D3Tab T = {};
    for (int q = 0; q < 4; ++q) {
        for (int t = 0; t < 6; ++t) {
            float acc = 0;
            for (int kp = 0; kp < 3; ++kp)
                acc += C[q][2*kp] * safeE(Ei, t - kp) + C[q][2*kp+1] * safeE(Oi, t - kp);
            T.d0[q][t] = acc;
        }
        for (int t = 0; t < 7; ++t) {
            float acc = 0;
            for (int kp = 0; kp < 3; ++kp)
                acc += C[q][2*kp] * safeE(Oi, t - kp) + C[q][2*kp+1] * safeE(Ei, t - kp - 1);
            T.d1[q][t] = acc;
        }
    }
    return T;
}

// 3-level fused synthesis: octet s reads u[s..s+6] (scalar DENSE 4B-stride loads)
// and writes 8 consecutive outputs via one stg256. u valid [0, 1030); max read 1029.
template<int HIA>
__device__ __forceinline__ void idwt3_fused(const float* __restrict__ u,
                                            float* __restrict__ out) {
    constexpr D3Tab T = make_d3<HIA>();
    for (int s = threadIdx.x; s < 1024; s += NT) {
        float v[7];
        #pragma unroll
        for (int t = 0; t < 7; ++t) v[t] = u[s + t];
        float4 a, b;
        {
            float y0 = v[0] * T.d0[0][0], y1 = v[0] * T.d0[1][0];
            float y2 = v[0] * T.d0[2][0], y3 = v[0] * T.d0[3][0];
            #pragma unroll
            for (int t = 1; t < 6; ++t) {
                y0 = fmaf(v[t], T.d0[0][t], y0);
                y1 = fmaf(v[t], T.d0[1][t], y1);
                y2 = fmaf(v[t], T.d0[2][t], y2);
                y3 = fmaf(v[t], T.d0[3][t], y3);
            }
            a = make_float4(y0, y1, y2, y3);
        }
        {
            float y0 = v[0] * T.d1[0][0], y1 = v[0] * T.d1[1][0];
            float y2 = v[0] * T.d1[2][0], y3 = v[0] * T.d1[3][0];
            #pragma unroll
            for (int t = 1; t < 7; ++t) {
                y0 = fmaf(v[t], T.d1[0][t], y0);
                y1 = fmaf(v[t], T.d1[1][t], y1);
                y2 = fmaf(v[t], T.d1[2][t], y2);
                y3 = fmaf(v[t], T.d1[3][t], y3);
            }
            b = make_float4(y0, y1, y2, y3);
        }
        stg256cs(out + 8 * s, a, b);
    }
}

__global__ void __launch_bounds__(NT, 6)
dwt_bands_kernel(const float* __restrict__ x, float* __restrict__ out) {
    extern __shared__ float sm[];
    float* a1 = sm + OFF_R0;
    float* d1 = sm + OFF_R1;
    float* a2 = sm + OFF_A2;    // R1 region, after d1 dies
    float* d2 = sm + OFF_D2;    // R1 region, after d1 dies
    float* a3 = sm + OFF_A3;    // R0 region, after a1 dies
    float* d3 = sm + OFF_D3;    // R0 region, after a1 dies

    const int row = blockIdx.x;
    const float* __restrict__ xr = x + (size_t)row * N;
    float* ob0 = out + (size_t)row * N;
    float* ob1 = ob0 + (size_t)NROW * N;
    float* ob2 = ob1 + (size_t)NROW * N;
    float* ob3 = ob2 + (size_t)NROW * N;

    // S1: level-1 analysis (global -> smem), streaming reads
    dwt_level<true>(xr, N, L1, a1, d1);
    __syncthreads();

    // S2a: band3 output (octet synthesis from d1, dense float4 loads + stg256)
    idwt_vec8f4<1>(d1, ob3);                  // 8192 -> global
    __syncthreads();                          // d1 dead

    // S2b: level-2 analysis into freed R1 region
    dwt_level<false>(a1, L1, L2, a2, d2);
    __syncthreads();                          // a1 dead

    // S3: band2 octet 2-level fused FIRST (drain global stores early),
    //     then level-3 analysis (into freed R0)
    idwt2_fused8<1>(d2, ob2);                 // 8192 -> global
    dwt_level<false>(a2, L2, L3, a3, d3);
    __syncthreads();                          // a2, d2 dead

    // S4: band0 & band1 3-level fused outputs (octet, dense scalar loads + stg256)
    idwt3_fused<0>(a3, ob0);                  // 8192 -> global
    idwt3_fused<1>(d3, ob1);                  // 8192 -> global
}

}  // namespace

extern "C" void kernel_launch(void* const* d_in, const int* in_sizes, int n_in,
                              void* d_out, int out_size) {
    const float* x = (const float*)d_in[0];
    float* out = (float*)d_out;
    constexpr int smem_bytes = SM_FLOATS * (int)sizeof(float);
    cudaFuncSetAttribute(dwt_bands_kernel,
                         cudaFuncAttributeMaxDynamicSharedMemorySize, smem_bytes);
    dwt_bands_kernel<<<NROW, NT, smem_bytes>>>(x, out);
}

// round 16
// speedup vs baseline: 1.0489x; 1.0489x over previous
#include <cuda_runtime.h>

#define W0 0.23037781330885523f
#define W1 0.7148465705525415f
#define W2 0.6308807679295904f
#define W3 (-0.02798376941698385f)
#define W4 (-0.18703481171888114f)
#define W5 0.030841381835986965f
#define W6 0.032883011666982945f
#define W7 (-0.010597401784997278f)

namespace {

constexpr int NROW = 2048;     // 32 * 64
constexpr int N    = 8192;
constexpr int L1   = 4099;     // dwt output lengths per level
constexpr int L2   = 2053;
constexpr int L3   = 1030;
constexpr int NT   = 384;      // threads per CTA (measured optimum: 5 CTAs/SM)

// shared memory: two regions, time-multiplexed.
//   R0 (4100): a1 (S1-S2b) -> a3 [0,1030) + d3 [1032,2062) (S3-S4)
//   R1 (4112): d1 (S1-S2a) -> a2 [0,2053) + d2 [2056,4109) (S2b-S3)
constexpr int OFF_R0 = 0;
constexpr int OFF_R1 = 4100;
constexpr int OFF_A3 = OFF_R0;
constexpr int OFF_D3 = OFF_R0 + 1032;
constexpr int OFF_A2 = OFF_R1;
constexpr int OFF_D2 = OFF_R1 + 2056;
constexpr int SM_FLOATS = 8212;    // 32848 B -> 5 CTAs/SM at 384 thr

__device__ __forceinline__ int symq(int q, int m) {
    q = (q < 0) ? (-q - 1) : q;
    return (q >= m) ? (2 * m - 1 - q) : q;
}

// 256-bit dense streaming global store (sm_100+): 8 consecutive floats, 32B-aligned.
__device__ __forceinline__ void stg256cs(float* p, float4 a, float4 b) {
    asm volatile("st.global.cs.v8.f32 [%0], {%1,%2,%3,%4,%5,%6,%7,%8};"
        :: "l"(p), "f"(a.x), "f"(a.y), "f"(a.z), "f"(a.w),
           "f"(b.x), "f"(b.y), "f"(b.z), "f"(b.w) : "memory");
}

// Scalar (boundary) analysis for one output index o.
__device__ __forceinline__ void dwt_scalar(const float* __restrict__ in, int m, int o,
                                           float& sA, float& sD) {
    const float RLO[8] = { W0,  W1,  W2,  W3,  W4,  W5,  W6,  W7};
    const float RHI[8] = { W7, -W6,  W5, -W4,  W3, -W2,  W1, -W0};
    const int base = 2 * o - 6;
    sA = 0.f; sD = 0.f;
    #pragma unroll
    for (int j = 0; j < 8; ++j) {
        float v = in[symq(base + j, m)];
        sA = fmaf(v, RLO[j], sA);
        sD = fmaf(v, RHI[j], sD);
    }
}

// One analysis level: lenOut = (m+5)/2 + 1. Pair-per-thread via 3x float4 loads
// (dense: 16B lane stride = load width). GLOB: input global read-once -> __ldcs.
template<bool GLOB>
__device__ __forceinline__ void dwt_level(const float* __restrict__ in, int m, int lenOut,
                                          float* __restrict__ oa, float* __restrict__ od) {
    const float4* __restrict__ in4 = reinterpret_cast<const float4*>(in);
    float2* __restrict__ oa2 = reinterpret_cast<float2*>(oa);
    float2* __restrict__ od2 = reinterpret_cast<float2*>(od);
    const int np = lenOut >> 1;
    for (int t = threadIdx.x; t < np; t += NT) {
        const int base = 4 * t - 6;
        float a0, d0, a1, d1;
        if (base >= 0 && base + 9 < m) {
            float4 q0, q1, q2;
            if (GLOB) {
                q0 = __ldcs(in4 + (t - 2));
                q1 = __ldcs(in4 + (t - 1));
                q2 = __ldcs(in4 + t);
            } else {
                q0 = in4[t - 2];
                q1 = in4[t - 1];
                q2 = in4[t];
            }
            a0 = fmaf(q0.z, W0, fmaf(q0.w, W1, fmaf(q1.x, W2, fmaf(q1.y, W3,
                 fmaf(q1.z, W4, fmaf(q1.w, W5, fmaf(q2.x, W6, q2.y * W7)))))));
            d0 = fmaf(q0.z, W7, fmaf(q0.w, -W6, fmaf(q1.x, W5, fmaf(q1.y, -W4,
                 fmaf(q1.z, W3, fmaf(q1.w, -W2, fmaf(q2.x, W1, q2.y * -W0)))))));
            a1 = fmaf(q1.x, W0, fmaf(q1.y, W1, fmaf(q1.z, W2, fmaf(q1.w, W3,
                 fmaf(q2.x, W4, fmaf(q2.y, W5, fmaf(q2.z, W6, q2.w * W7)))))));
            d1 = fmaf(q1.x, W7, fmaf(q1.y, -W6, fmaf(q1.z, W5, fmaf(q1.w, -W4,
                 fmaf(q2.x, W3, fmaf(q2.y, -W2, fmaf(q2.z, W1, q2.w * -W0)))))));
        } else {
            dwt_scalar(in, m, 2 * t,     a0, d0);
            dwt_scalar(in, m, 2 * t + 1, a1, d1);
        }
        oa2[t] = make_float2(a0, a1);
        od2[t] = make_float2(d0, d1);
    }
    if ((lenOut & 1) && threadIdx.x == 0) {   // odd tail output
        float a, d;
        dwt_scalar(in, m, lenOut - 1, a, d);
        oa[lenOut - 1] = a;
        od[lenOut - 1] = d;
    }
}

// One synthesis quad (4 outputs) from v0..v4 = in[2q..2q+4].
template<int HI>
__device__ __forceinline__ float4 idwt_quad(float v0, float v1, float v2, float v3, float v4) {
    const float E0 = HI ?  W1 : W6, E1 = HI ?  W3 : W4;
    const float E2 = HI ?  W5 : W2, E3 = HI ?  W7 : W0;
    const float O0 = HI ? -W0 : W7, O1 = HI ? -W2 : W5;
    const float O2 = HI ? -W4 : W3, O3 = HI ? -W6 : W1;
    float4 r;
    r.x = fmaf(v0, E0, fmaf(v1, E1, fmaf(v2, E2, v3 * E3)));
    r.y = fmaf(v0, O0, fmaf(v1, O1, fmaf(v2, O2, v3 * O3)));
    r.z = fmaf(v1, E0, fmaf(v2, E1, fmaf(v3, E2, v4 * E3)));
    r.w = fmaf(v1, O0, fmaf(v2, O1, fmaf(v3, O2, v4 * O3)));
    return r;
}

// Band3 single synthesis level, octet/thread: input m=4099 (4096 pairs = 1024 octets
// exactly). Octet s needs in[4s..4s+6], loaded as 2x DENSE float4 (16B stride = width).
// Max s=1023: reads in4[1024] = in[4096..4099] <= region 4112 (slack ok).
template<int HI>
__device__ __forceinline__ void idwt_vec8f4(const float* __restrict__ in,
                                            float* __restrict__ out) {
    const float4* __restrict__ in4 = reinterpret_cast<const float4*>(in);
    for (int s = threadIdx.x; s < 1024; s += NT) {
        float4 q0 = in4[s];        // in[4s..4s+3]
        float4 q1 = in4[s + 1];    // in[4s+4..4s+7]
        float4 a = idwt_quad<HI>(q0.x, q0.y, q0.z, q0.w, q1.x);
        float4 b = idwt_quad<HI>(q0.z, q0.w, q1.x, q1.y, q1.z);
        stg256cs(out + 8 * s, a, b);
    }
}

// Fused TWO synthesis levels (stage A = HIA, stage B = LO), octet/thread.
// Octet s = groups 2s,2s+1, window in[2s..2s+6] = in2[s..s+3] (DENSE float2,
// 8B stride = width). Max s=1023: in2[1026] -> in[2052..2053], slack ok.
template<int HIA>
__device__ __forceinline__ void idwt2_fused8(const float* __restrict__ in,
                                             float* __restrict__ out) {
    const float EA0 = HIA ?  W1 : W6, EA1 = HIA ?  W3 : W4;
    const float EA2 = HIA ?  W5 : W2, EA3 = HIA ?  W7 : W0;
    const float OA0 = HIA ? -W0 : W7, OA1 = HIA ? -W2 : W5;
    const float OA2 = HIA ? -W4 : W3, OA3 = HIA ? -W6 : W1;
    const float EB0 = W6, EB1 = W4, EB2 = W2, EB3 = W0;
    const float OB0 = W7, OB1 = W5, OB2 = W3, OB3 = W1;
    const float C00 = EB0*EA0 + EB1*OA0;
    const float C01 = EB0*EA1 + EB1*OA1 + EB2*EA0 + EB3*OA0;
    const float C02 = EB0*EA2 + EB1*OA2 + EB2*EA1 + EB3*OA1;
    const float C03 = EB0*EA3 + EB1*OA3 + EB2*EA2 + EB3*OA2;
    const float C04 =                     EB2*EA3 + EB3*OA3;
    const float C10 = OB0*EA0 + OB1*OA0;
    const float C11 = OB0*EA1 + OB1*OA1 + OB2*EA0 + OB3*OA0;
    const float C12 = OB0*EA2 + OB1*OA2 + OB2*EA1 + OB3*OA1;
    const float C13 = OB0*EA3 + OB1*OA3 + OB2*EA2 + OB3*OA2;
    const float C14 =                     OB2*EA3 + OB3*OA3;
    const float C20 = EB0*OA0;
    const float C21 = EB0*OA1 + EB1*EA0 + EB2*OA0;
    const float C22 = EB0*OA2 + EB1*EA1 + EB2*OA1 + EB3*EA0;
    const float C23 = EB0*OA3 + EB1*EA2 + EB2*OA2 + EB3*EA1;
    const float C24 =           EB1*EA3 + EB2*OA3 + EB3*EA2;
    const float C25 =                                EB3*EA3;
    const float C30 = OB0*OA0;
    const float C31 = OB0*OA1 + OB1*EA0 + OB2*OA0;
    const float C32 = OB0*OA2 + OB1*EA1 + OB2*OA1 + OB3*EA0;
    const float C33 = OB0*OA3 + OB1*EA2 + OB2*OA2 + OB3*EA1;
    const float C34 =           OB1*EA3 + OB2*OA3 + OB3*EA2;
    const float C35 =                                OB3*EA3;

    const float2* __restrict__ in2 = reinterpret_cast<const float2*>(in);
    for (int s = threadIdx.x; s < 1024; s += NT) {
        float2 w0 = in2[s];           // in[2s],   in[2s+1]
        float2 w1 = in2[s + 1];       // in[2s+2], in[2s+3]
        float2 w2 = in2[s + 2];       // in[2s+4], in[2s+5]
        float2 w3 = in2[s + 3];       // in[2s+6], in[2s+7] (slack)
        float v0 = w0.x, v1 = w0.y, v2 = w1.x, v3 = w1.y;
        float v4 = w2.x, v5 = w2.y, v6 = w3.x;
        float4 oA, oB;
        oA.x = fmaf(v0, C00, fmaf(v1, C01, fmaf(v2, C02, fmaf(v3, C03, v4 * C04))));
        oA.y = fmaf(v0, C10, fmaf(v1, C11, fmaf(v2, C12, fmaf(v3, C13, v4 * C14))));
        oA.z = fmaf(v0, C20, fmaf(v1, C21, fmaf(v2, C22,
               fmaf(v3, C23, fmaf(v4, C24, v5 * C25)))));
        oA.w = fmaf(v0, C30, fmaf(v1, C31, fmaf(v2, C32,
               fmaf(v3, C33, fmaf(v4, C34, v5 * C35)))));
        oB.x = fmaf(v1, C00, fmaf(v2, C01, fmaf(v3, C02, fmaf(v4, C03, v5 * C04))));
        oB.y = fmaf(v1, C10, fmaf(v2, C11, fmaf(v3, C12, fmaf(v4, C13, v5 * C14))));
        oB.z = fmaf(v1, C20, fmaf(v2, C21, fmaf(v3, C22,
               fmaf(v4, C23, fmaf(v5, C24, v6 * C25)))));
        oB.w = fmaf(v1, C30, fmaf(v2, C31, fmaf(v3, C32,
               fmaf(v4, C33, fmaf(v5, C34, v6 * C35)))));
        stg256cs(out + 8 * s, oA, oB);
    }
}

// ---- 3-level fused synthesis tables (inner HIA, then LO, then LO) ----
struct D3Tab { float d0[4][6]; float d1[4][7]; };

__host__ __device__ constexpr float safeE(const float* a, int i) {
    return (i >= 0 && i < 4) ? a[i] : 0.0f;
}

template<int HIA>
__host__ __device__ constexpr D3Tab make_d3() {
    float Ei[4] = {0, 0, 0, 0}, Oi[4] = {0, 0, 0, 0};
    if (HIA) {
        Ei[0] = W1; Ei[1] = W3; Ei[2] = W5; Ei[3] = W7;
        Oi[0] = -W0; Oi[1] = -W2; Oi[2] = -W4; Oi[3] = -W6;
    } else {
        Ei[0] = W6; Ei[1] = W4; Ei[2] = W2; Ei[3] = W0;
        Oi[0] = W7; Oi[1] = W5; Oi[2] = W3; Oi[3] = W1;
    }
    const float EA[4] = {W6, W4, W2, W0}, OA[4] = {W7, W5, W3, W1};
    const float EB[4] = {W6, W4, W2, W0}, OB[4] = {W7, W5, W3, W1};
    float C[4][6] = {};
    for (int k = 0; k < 6; ++k) {
        float c0 = 0, c1 = 0, c2 = 0, c3 = 0;
        for (int kp = 0; kp < 2; ++kp) {
            c0 += EB[2*kp] * safeE(EA, k - kp) + EB[2*kp+1] * safeE(OA, k - kp);
            c1 += OB[2*kp] * safeE(EA, k - kp) + OB[2*kp+1] * safeE(OA, k - kp);
            c2 += EB[2*kp] * safeE(OA, k - kp) + EB[2*kp+1] * safeE(EA, k - kp - 1);
            c3 += OB[2*kp] * safeE(OA, k - kp) + OB[2*kp+1] * safeE(EA, k - kp - 1);
        }
        C[0][k] = c0; C[1][k] = c1; C[2][k] = c2; C[3][k] = c3;
    }
    D3Tab T = {};
    for (int q = 0; q < 4; ++q) {
        for (int t = 0; t < 6; ++t) {
            float acc = 0;
            for (int kp = 0; kp < 3; ++kp)
                acc += C[q][2*kp] * safeE(Ei, t - kp) + C[q][2*kp+1] * safeE(Oi, t - kp);
            T.d0[q][t] = acc;
        }
        for (int t = 0; t < 7; ++t) {
            float acc = 0;
            for (int kp = 0; kp < 3; ++kp)
                acc += C[q][2*kp] * safeE(Oi, t - kp) + C[q][2*kp+1] * safeE(Ei, t - kp - 1);
            T.d1[q][t] = acc;
        }
    }
    return T;
}

// 3-level fused synthesis: octet s reads u[s..s+6] (scalar DENSE 4B-stride loads)
// and writes 8 consecutive outputs via one stg256. u valid [0, 1030); max read 1029.
template<int HIA>
__device__ __forceinline__ void idwt3_fused(const float* __restrict__ u,
                                            float* __restrict__ out) {
    constexpr D3Tab T = make_d3<HIA>();
    for (int s = threadIdx.x; s < 1024; s += NT) {
        float v[7];
        #pragma unroll
        for (int t = 0; t < 7; ++t) v[t] = u[s + t];
        float4 a, b;
        {
            float y0 = v[0] * T.d0[0][0], y1 = v[0] * T.d0[1][0];
            float y2 = v[0] * T.d0[2][0], y3 = v[0] * T.d0[3][0];
            #pragma unroll
            for (int t = 1; t < 6; ++t) {
                y0 = fmaf(v[t], T.d0[0][t], y0);
                y1 = fmaf(v[t], T.d0[1][t], y1);
                y2 = fmaf(v[t], T.d0[2][t], y2);
                y3 = fmaf(v[t], T.d0[3][t], y3);
            }
            a = make_float4(y0, y1, y2, y3);
        }
        {
            float y0 = v[0] * T.d1[0][0], y1 = v[0] * T.d1[1][0];
            float y2 = v[0] * T.d1[2][0], y3 = v[0] * T.d1[3][0];
            #pragma unroll
            for (int t = 1; t < 7; ++t) {
                y0 = fmaf(v[t], T.d1[0][t], y0);
                y1 = fmaf(v[t], T.d1[1][t], y1);
                y2 = fmaf(v[t], T.d1[2][t], y2);
                y3 = fmaf(v[t], T.d1[3][t], y3);
            }
            b = make_float4(y0, y1, y2, y3);
        }
        stg256cs(out + 8 * s, a, b);
    }
}

__global__ void __launch_bounds__(NT, 5)
dwt_bands_kernel(const float* __restrict__ x, float* __restrict__ out) {
    extern __shared__ float sm[];
    float* a1 = sm + OFF_R0;
    float* d1 = sm + OFF_R1;
    float* a2 = sm + OFF_A2;    // R1 region, after d1 dies
    float* d2 = sm + OFF_D2;    // R1 region, after d1 dies
    float* a3 = sm + OFF_A3;    // R0 region, after a1 dies
    float* d3 = sm + OFF_D3;    // R0 region, after a1 dies

    const int row = blockIdx.x;
    const float* __restrict__ xr = x + (size_t)row * N;
    float* ob0 = out + (size_t)row * N;
    float* ob1 = ob0 + (size_t)NROW * N;
    float* ob2 = ob1 + (size_t)NROW * N;
    float* ob3 = ob2 + (size_t)NROW * N;

    // S1: level-1 analysis (global -> smem), streaming reads
    dwt_level<true>(xr, N, L1, a1, d1);
    __syncthreads();

    // S2a: band3 output (octet synthesis from d1, dense float4 loads + stg256)
    idwt_vec8f4<1>(d1, ob3);                  // 8192 -> global
    __syncthreads();                          // d1 dead

    // S2b: level-2 analysis into freed R1 region
    dwt_level<false>(a1, L1, L2, a2, d2);
    __syncthreads();                          // a1 dead

    // S3: band2 octet 2-level fused FIRST (drain global stores behind analysis),
    //     then level-3 analysis (into freed R0)
    idwt2_fused8<1>(d2, ob2);                 // 8192 -> global
    dwt_level<false>(a2, L2, L3, a3, d3);
    __syncthreads();                          // a2, d2 dead

    // S4: band0 & band1 3-level fused outputs (octet, dense scalar loads + stg256)
    idwt3_fused<0>(a3, ob0);                  // 8192 -> global
    idwt3_fused<1>(d3, ob1);                  // 8192 -> global
}

}  // namespace

extern "C" void kernel_launch(void* const* d_in, const int* in_sizes, int n_in,
                              void* d_out, int out_size) {
    const float* x = (const float*)d_in[0];
    float* out = (float*)d_out;
    constexpr int smem_bytes = SM_FLOATS * (int)sizeof(float);
    cudaFuncSetAttribute(dwt_bands_kernel,
                         cudaFuncAttributeMaxDynamicSharedMemorySize, smem_bytes);
    dwt_bands_kernel<<<NROW, NT, smem_bytes>>>(x, out);
}